// round 10
// baseline (speedup 1.0000x reference)
#include <cuda_runtime.h>
#include <cuda_fp16.h>
#include <cstdint>

#define N 4096
#define K 512
#define KSEL 31

__device__ float  g_d2[(size_t)N * N];
__device__ float  g_sq[N];
__device__ float  g_t[N];
__device__ float  g_inv[N];
__device__ __half g_Xhi[(size_t)N * K];
__device__ __half g_Xlo[(size_t)N * K];

__device__ __forceinline__ uint32_t smem_u32(const void* p) {
    uint32_t a;
    asm("{ .reg .u64 t; cvta.to.shared.u64 t, %1; cvt.u32.u64 %0, t; }" : "=r"(a) : "l"(p));
    return a;
}
#define CP_COMMIT() asm volatile("cp.async.commit_group;" ::: "memory")
#define CP_WAIT(n)  asm volatile("cp.async.wait_group %0;" :: "n"(n) : "memory")

__device__ __forceinline__ void mma16(float* c, const uint32_t* a, const uint32_t* b) {
    asm("mma.sync.aligned.m16n8k16.row.col.f32.f16.f16.f32 "
        "{%0,%1,%2,%3}, {%4,%5,%6,%7}, {%8,%9}, {%0,%1,%2,%3};"
        : "+f"(c[0]), "+f"(c[1]), "+f"(c[2]), "+f"(c[3])
        : "r"(a[0]), "r"(a[1]), "r"(a[2]), "r"(a[3]), "r"(b[0]), "r"(b[1]));
}
#define LDSM4(r, addr) \
    asm volatile("ldmatrix.sync.aligned.m8n8.x4.shared.b16 {%0,%1,%2,%3}, [%4];" \
        : "=r"((r)[0]), "=r"((r)[1]), "=r"((r)[2]), "=r"((r)[3]) : "r"(addr))

#define SWI(i) ((((i) >> 2) + (((i) & 3) << 3)) & 31)
__device__ __forceinline__ uint32_t swz(int r, int c) {
    return (uint32_t)(r * 64 + ((c ^ ((r >> 1) & 3)) << 4));
}

// ---------------- fused convert + norms ----------------
__global__ void __launch_bounds__(128) convnorm_kernel(const float* __restrict__ X) {
    int row = blockIdx.x, t = threadIdx.x;
    float4 v = reinterpret_cast<const float4*>(X + (size_t)row * K)[t];
    __half hx = __float2half_rn(v.x), hy = __float2half_rn(v.y);
    __half hz = __float2half_rn(v.z), hw = __float2half_rn(v.w);
    __half lx = __float2half_rn(v.x - __half2float(hx));
    __half ly = __float2half_rn(v.y - __half2float(hy));
    __half lz = __float2half_rn(v.z - __half2float(hz));
    __half lw = __float2half_rn(v.w - __half2float(hw));
    __half2* ph = reinterpret_cast<__half2*>(g_Xhi + (size_t)row * K);
    __half2* pl = reinterpret_cast<__half2*>(g_Xlo + (size_t)row * K);
    ph[t * 2 + 0] = __halves2half2(hx, hy); ph[t * 2 + 1] = __halves2half2(hz, hw);
    pl[t * 2 + 0] = __halves2half2(lx, ly); pl[t * 2 + 1] = __halves2half2(lz, lw);

    float s = v.x * v.x + v.y * v.y + v.z * v.z + v.w * v.w;
    #pragma unroll
    for (int o = 16; o; o >>= 1) s += __shfl_xor_sync(0xffffffffu, s, o);
    __shared__ float ws[4];
    if ((t & 31) == 0) ws[t >> 5] = s;
    __syncthreads();
    if (t == 0) g_sq[row] = ws[0] + ws[1] + ws[2] + ws[3];
}

// ---------------- GEMM via mma.sync fp16 (3-term split) ----------------
#define STG 32768
#define BUF 8192

__device__ __forceinline__ void cp_stage(char* sm, int s, int it, int tid, int i0, int j0) {
    char* base = sm + s * STG;
    #pragma unroll
    for (int q = 0; q < 8; q++) {
        int idx = tid + 256 * q;
        int buf = idx >> 9, r = (idx >> 2) & 127, c = idx & 3;
        const __half* src = ((buf & 1) ? g_Xlo : g_Xhi)
                          + (size_t)(((buf < 2) ? i0 : j0) + r) * K + it * 32 + c * 8;
        uint32_t dst = smem_u32(base + buf * BUF) + swz(r, c);
        asm volatile("cp.async.cg.shared.global [%0], [%1], 16;" :: "r"(dst), "l"(src));
    }
}

__global__ void __launch_bounds__(256, 2) gemm_kernel() {
    __shared__ float s_sqi[128], s_sqj[128];
    extern __shared__ char sm[];

    int t = blockIdx.x;
    int by = (int)(32.5f - sqrtf(32.5f * 32.5f - 2.0f * (float)t));
    while (by * (65 - by) / 2 > t) by--;
    while ((by + 1) * (64 - by) / 2 <= t) by++;
    int bx = by + (t - by * (65 - by) / 2);
    const int i0 = by * 128, j0 = bx * 128;

    const int tid = threadIdx.x;
    const int warp = tid >> 5, lane = tid & 31;
    const int wm = warp & 1, wn = warp >> 1;
    const int l4 = lane >> 2, lm = lane & 3;

    if (tid < 128) { s_sqi[tid] = g_sq[i0 + tid]; s_sqj[tid] = g_sq[j0 + tid]; }

    const int rA = wm * 64 + (lane & 7) + ((lane >> 3) & 1) * 8;
    const int cA = (lane >> 4) & 1;
    const int rB = wn * 32 + (lane & 7) + ((lane >> 4) & 1) * 8;
    const int cB = (lane >> 3) & 1;

    float acc[4][4][4];
    #pragma unroll
    for (int a = 0; a < 4; a++)
        #pragma unroll
        for (int b = 0; b < 4; b++)
            #pragma unroll
            for (int c = 0; c < 4; c++) acc[a][b][c] = 0.f;

    cp_stage(sm, 0, 0, tid, i0, j0);
    CP_COMMIT();

    for (int it = 0; it < 16; it++) {
        if (it + 1 < 16) { cp_stage(sm, 1 - (it & 1), it + 1, tid, i0, j0); CP_COMMIT(); CP_WAIT(1); }
        else CP_WAIT(0);
        __syncthreads();

        uint32_t Ah = smem_u32(sm + (it & 1) * STG);
        uint32_t Al = Ah + BUF, Bh = Ah + 2 * BUF, Bl = Ah + 3 * BUF;
        #pragma unroll
        for (int ks = 0; ks < 2; ks++) {
            uint32_t af[4][4], bh[4][2], bl[4][2];
            #pragma unroll
            for (int mt = 0; mt < 4; mt++) LDSM4(af[mt], Ah + swz(rA + mt * 16, cA + 2 * ks));
            #pragma unroll
            for (int p = 0; p < 2; p++) {
                uint32_t r4[4];
                LDSM4(r4, Bh + swz(rB + p * 16, cB + 2 * ks));
                bh[2 * p][0] = r4[0]; bh[2 * p][1] = r4[1];
                bh[2 * p + 1][0] = r4[2]; bh[2 * p + 1][1] = r4[3];
                LDSM4(r4, Bl + swz(rB + p * 16, cB + 2 * ks));
                bl[2 * p][0] = r4[0]; bl[2 * p][1] = r4[1];
                bl[2 * p + 1][0] = r4[2]; bl[2 * p + 1][1] = r4[3];
            }
            #pragma unroll
            for (int mt = 0; mt < 4; mt++)
                #pragma unroll
                for (int nt = 0; nt < 4; nt++) mma16(acc[mt][nt], af[mt], bh[nt]);   // hi*hi
            #pragma unroll
            for (int mt = 0; mt < 4; mt++)
                #pragma unroll
                for (int nt = 0; nt < 4; nt++) mma16(acc[mt][nt], af[mt], bl[nt]);   // hi*lo
            #pragma unroll
            for (int mt = 0; mt < 4; mt++) LDSM4(af[mt], Al + swz(rA + mt * 16, cA + 2 * ks));
            #pragma unroll
            for (int mt = 0; mt < 4; mt++)
                #pragma unroll
                for (int nt = 0; nt < 4; nt++) mma16(acc[mt][nt], af[mt], bh[nt]);   // lo*hi
        }
        __syncthreads();
    }

    float* epi = reinterpret_cast<float*>(sm);
    #pragma unroll
    for (int mt = 0; mt < 4; mt++)
        #pragma unroll
        for (int nt = 0; nt < 4; nt++) {
            int r0 = wm * 64 + mt * 16 + l4;
            int c0 = wn * 32 + nt * 8 + lm * 2;
            #pragma unroll
            for (int i = 0; i < 4; i++) {
                int r = r0 + ((i >> 1) << 3);
                int c = c0 + (i & 1);
                float d = fmaxf(fmaf(-2.0f, acc[mt][nt][i], s_sqi[r] + s_sqj[c]), 0.0f);
                epi[r * 128 + ((c & ~31) | ((c ^ SWI(r)) & 31))] = d;
            }
        }
    __syncthreads();
    for (int idx = tid; idx < 4096; idx += 256) {
        int r = idx >> 5, c4 = (idx & 31) << 2, sw = SWI(r);
        float4 o;
        o.x = epi[r * 128 + (((c4 + 0) & ~31) | (((c4 + 0) ^ sw) & 31))];
        o.y = epi[r * 128 + (((c4 + 1) & ~31) | (((c4 + 1) ^ sw) & 31))];
        o.z = epi[r * 128 + (((c4 + 2) & ~31) | (((c4 + 2) ^ sw) & 31))];
        o.w = epi[r * 128 + (((c4 + 3) & ~31) | (((c4 + 3) ^ sw) & 31))];
        *reinterpret_cast<float4*>(g_d2 + (size_t)(i0 + r) * N + j0 + c4) = o;
    }
    for (int idx = tid; idx < 4096; idx += 256) {
        int c = idx >> 5, r4 = (idx & 31) << 2;
        float4 o;
        o.x = epi[(r4 + 0) * 128 + ((c & ~31) | ((c ^ SWI(r4 + 0)) & 31))];
        o.y = epi[(r4 + 1) * 128 + ((c & ~31) | ((c ^ SWI(r4 + 1)) & 31))];
        o.z = epi[(r4 + 2) * 128 + ((c & ~31) | ((c ^ SWI(r4 + 2)) & 31))];
        o.w = epi[(r4 + 3) * 128 + ((c & ~31) | ((c ^ SWI(r4 + 3)) & 31))];
        *reinterpret_cast<float4*>(g_d2 + (size_t)(j0 + c) * N + i0 + r4) = o;
    }
}

// ---------------- select: 512 threads, linear bins + exact in-bin rank ----------------
__global__ void __launch_bounds__(512) select_kernel() {
    const int row = blockIdx.x, tid = threadIdx.x;
    const int warp = tid >> 5, lane = tid & 31;
    __shared__ unsigned bins[2048];
    __shared__ float cand[1024];
    __shared__ unsigned s_cnt, s_bin, s_below;
    __shared__ unsigned wsum[16];
    __shared__ float s_tv;

    float f[8];
    {
        const float4* p = reinterpret_cast<const float4*>(g_d2 + (size_t)row * N);
        #pragma unroll
        for (int q = 0; q < 2; q++) {
            float4 v = p[tid + 512 * q];
            f[q * 4 + 0] = v.x; f[q * 4 + 1] = v.y; f[q * 4 + 2] = v.z; f[q * 4 + 3] = v.w;
        }
    }
    #pragma unroll
    for (int i = 0; i < 4; i++) bins[tid + 512 * i] = 0;
    if (tid == 0) s_cnt = 0;
    __syncthreads();
    #pragma unroll
    for (int q = 0; q < 8; q++) atomicAdd(&bins[min((int)f[q], 2047)], 1u);
    __syncthreads();

    unsigned b4[4], loc = 0;
    #pragma unroll
    for (int i = 0; i < 4; i++) { b4[i] = bins[tid * 4 + i]; loc += b4[i]; }
    unsigned sc = loc;
    #pragma unroll
    for (int o = 1; o < 32; o <<= 1) { unsigned x = __shfl_up_sync(0xffffffffu, sc, o); if (lane >= o) sc += x; }
    if (lane == 31) wsum[warp] = sc;
    __syncthreads();
    if (tid < 32) {
        unsigned v = (lane < 16) ? wsum[lane] : 0u, s = v;
        #pragma unroll
        for (int o = 1; o < 16; o <<= 1) { unsigned x = __shfl_up_sync(0xffffffffu, s, o); if (lane >= o) s += x; }
        if (lane < 16) wsum[lane] = s - v;
    }
    __syncthreads();
    unsigned before = wsum[warp] + sc - loc;
    if (before < KSEL && before + loc >= KSEL) {
        unsigned cum = before;
        #pragma unroll
        for (int i = 0; i < 4; i++) {
            if (cum + b4[i] >= KSEL) { s_bin = tid * 4 + i; s_below = cum; break; }
            cum += b4[i];
        }
    }
    __syncthreads();
    const unsigned b = s_bin, rp = KSEL - s_below;
    #pragma unroll
    for (int q = 0; q < 8; q++)
        if ((unsigned)min((int)f[q], 2047) == b) {
            unsigned id = atomicAdd(&s_cnt, 1u);
            if (id < 1024) cand[id] = f[q];
        }
    __syncthreads();
    const unsigned c = min(s_cnt, 1024u);
    for (unsigned i = tid; i < c; i += 512) {
        float v = cand[i];
        unsigned less = 0, eq = 0;
        for (unsigned j = 0; j < c; j++) { float w = cand[j]; less += (w < v); eq += (w == v); }
        if (less < rp && less + eq >= rp) s_tv = v;
    }
    __syncthreads();
    if (tid == 0) {
        float tv = s_tv;
        g_t[row] = tv;
        float scale = sqrtf(fmaxf(tv, 1e-12f));
        float denom = fmaxf(scale, 1e-8f);
        g_inv[row] = 1.0f / (denom * denom);
    }
}

// ---------------- output: branch-skip exp (mask density ~1.5%) ----------------
__global__ void __launch_bounds__(256) out_kernel(float* __restrict__ outp) {
    size_t gid = (size_t)blockIdx.x * 256 + threadIdx.x;
    int row = (int)(gid >> 9);
    int c0  = (int)(gid & 511) << 3;

    float ti = g_t[row], invi = g_inv[row];
    const float* dr = g_d2 + (size_t)row * N + c0;
    float4 d0 = *reinterpret_cast<const float4*>(dr);
    float4 d1 = *reinterpret_cast<const float4*>(dr + 4);
    float4 t0 = *reinterpret_cast<const float4*>(g_t + c0);
    float4 t1 = *reinterpret_cast<const float4*>(g_t + c0 + 4);
    float4 i0 = *reinterpret_cast<const float4*>(g_inv + c0);
    float4 i1 = *reinterpret_cast<const float4*>(g_inv + c0 + 4);

    float4 o0, o1;
    // Gate on a single compare; only ~1.5% of elements enter, so ~62% of the
    // 8 sites per warp have zero active lanes and skip MUFU/FMA entirely.
    #define OUT1(o, dv, tv, iv) do {                                  \
        float _r = 0.f;                                               \
        if (dv <= fmaxf(ti, tv)) {                                    \
            if (dv <= ti) _r += __expf(-dv * invi);                   \
            if (dv <= tv) _r += __expf(-dv * iv);                     \
        }                                                             \
        o = 0.5f * _r;                                                \
    } while (0)
    OUT1(o0.x, d0.x, t0.x, i0.x); OUT1(o0.y, d0.y, t0.y, i0.y);
    OUT1(o0.z, d0.z, t0.z, i0.z); OUT1(o0.w, d0.w, t0.w, i0.w);
    OUT1(o1.x, d1.x, t1.x, i1.x); OUT1(o1.y, d1.y, t1.y, i1.y);
    OUT1(o1.z, d1.z, t1.z, i1.z); OUT1(o1.w, d1.w, t1.w, i1.w);
    #undef OUT1
    float* po = outp + (size_t)row * N + c0;
    *reinterpret_cast<float4*>(po)     = o0;
    *reinterpret_cast<float4*>(po + 4) = o1;
}

// ---------------- launch ----------------
extern "C" void kernel_launch(void* const* d_in, const int* in_sizes, int n_in,
                              void* d_out, int out_size) {
    const float* X = (const float*)d_in[0];
    float* outp = (float*)d_out;
    const int smem = 2 * STG;
    cudaFuncSetAttribute(gemm_kernel, cudaFuncAttributeMaxDynamicSharedMemorySize, smem);

    convnorm_kernel<<<N, 128>>>(X);
    gemm_kernel<<<528, 256, smem>>>();
    select_kernel<<<N, 512>>>();
    out_kernel<<<(size_t)N * N / 8 / 256, 256>>>(outp);
}

// round 11
// speedup vs baseline: 1.0343x; 1.0343x over previous
#include <cuda_runtime.h>
#include <cuda_fp16.h>
#include <cstdint>

#define N 4096
#define K 512
#define KSEL 31

__device__ float  g_d2[(size_t)N * N];
__device__ float  g_sq[N];
__device__ __half g_Xhi[(size_t)N * K];
__device__ __half g_Xlo[(size_t)N * K];

__device__ __forceinline__ uint32_t smem_u32(const void* p) {
    uint32_t a;
    asm("{ .reg .u64 t; cvta.to.shared.u64 t, %1; cvt.u32.u64 %0, t; }" : "=r"(a) : "l"(p));
    return a;
}
#define CP_COMMIT() asm volatile("cp.async.commit_group;" ::: "memory")
#define CP_WAIT(n)  asm volatile("cp.async.wait_group %0;" :: "n"(n) : "memory")

__device__ __forceinline__ void mma16(float* c, const uint32_t* a, const uint32_t* b) {
    asm("mma.sync.aligned.m16n8k16.row.col.f32.f16.f16.f32 "
        "{%0,%1,%2,%3}, {%4,%5,%6,%7}, {%8,%9}, {%0,%1,%2,%3};"
        : "+f"(c[0]), "+f"(c[1]), "+f"(c[2]), "+f"(c[3])
        : "r"(a[0]), "r"(a[1]), "r"(a[2]), "r"(a[3]), "r"(b[0]), "r"(b[1]));
}
#define LDSM4(r, addr) \
    asm volatile("ldmatrix.sync.aligned.m8n8.x4.shared.b16 {%0,%1,%2,%3}, [%4];" \
        : "=r"((r)[0]), "=r"((r)[1]), "=r"((r)[2]), "=r"((r)[3]) : "r"(addr))

#define SWI(i) ((((i) >> 2) + (((i) & 3) << 3)) & 31)
__device__ __forceinline__ uint32_t swz(int r, int c) {
    return (uint32_t)(r * 64 + ((c ^ ((r >> 1) & 3)) << 4));
}

// ---------------- zero-fill output ----------------
__global__ void __launch_bounds__(256) zero_kernel(float* __restrict__ outp) {
    size_t gid = (size_t)blockIdx.x * 256 + threadIdx.x;
    float4 z = make_float4(0.f, 0.f, 0.f, 0.f);
    reinterpret_cast<float4*>(outp)[gid * 2]     = z;
    reinterpret_cast<float4*>(outp)[gid * 2 + 1] = z;
}

// ---------------- fused convert + norms ----------------
__global__ void __launch_bounds__(128) convnorm_kernel(const float* __restrict__ X) {
    int row = blockIdx.x, t = threadIdx.x;
    float4 v = reinterpret_cast<const float4*>(X + (size_t)row * K)[t];
    __half hx = __float2half_rn(v.x), hy = __float2half_rn(v.y);
    __half hz = __float2half_rn(v.z), hw = __float2half_rn(v.w);
    __half lx = __float2half_rn(v.x - __half2float(hx));
    __half ly = __float2half_rn(v.y - __half2float(hy));
    __half lz = __float2half_rn(v.z - __half2float(hz));
    __half lw = __float2half_rn(v.w - __half2float(hw));
    __half2* ph = reinterpret_cast<__half2*>(g_Xhi + (size_t)row * K);
    __half2* pl = reinterpret_cast<__half2*>(g_Xlo + (size_t)row * K);
    ph[t * 2 + 0] = __halves2half2(hx, hy); ph[t * 2 + 1] = __halves2half2(hz, hw);
    pl[t * 2 + 0] = __halves2half2(lx, ly); pl[t * 2 + 1] = __halves2half2(lz, lw);

    float s = v.x * v.x + v.y * v.y + v.z * v.z + v.w * v.w;
    #pragma unroll
    for (int o = 16; o; o >>= 1) s += __shfl_xor_sync(0xffffffffu, s, o);
    __shared__ float ws[4];
    if ((t & 31) == 0) ws[t >> 5] = s;
    __syncthreads();
    if (t == 0) g_sq[row] = ws[0] + ws[1] + ws[2] + ws[3];
}

// ---------------- GEMM via mma.sync fp16 (3-term split) ----------------
#define STG 32768
#define BUF 8192

__device__ __forceinline__ void cp_stage(char* sm, int s, int it, int tid, int i0, int j0) {
    char* base = sm + s * STG;
    #pragma unroll
    for (int q = 0; q < 8; q++) {
        int idx = tid + 256 * q;
        int buf = idx >> 9, r = (idx >> 2) & 127, c = idx & 3;
        const __half* src = ((buf & 1) ? g_Xlo : g_Xhi)
                          + (size_t)(((buf < 2) ? i0 : j0) + r) * K + it * 32 + c * 8;
        uint32_t dst = smem_u32(base + buf * BUF) + swz(r, c);
        asm volatile("cp.async.cg.shared.global [%0], [%1], 16;" :: "r"(dst), "l"(src));
    }
}

__global__ void __launch_bounds__(256, 2) gemm_kernel() {
    __shared__ float s_sqi[128], s_sqj[128];
    extern __shared__ char sm[];

    int t = blockIdx.x;
    int by = (int)(32.5f - sqrtf(32.5f * 32.5f - 2.0f * (float)t));
    while (by * (65 - by) / 2 > t) by--;
    while ((by + 1) * (64 - by) / 2 <= t) by++;
    int bx = by + (t - by * (65 - by) / 2);
    const int i0 = by * 128, j0 = bx * 128;

    const int tid = threadIdx.x;
    const int warp = tid >> 5, lane = tid & 31;
    const int wm = warp & 1, wn = warp >> 1;
    const int l4 = lane >> 2, lm = lane & 3;

    if (tid < 128) { s_sqi[tid] = g_sq[i0 + tid]; s_sqj[tid] = g_sq[j0 + tid]; }

    const int rA = wm * 64 + (lane & 7) + ((lane >> 3) & 1) * 8;
    const int cA = (lane >> 4) & 1;
    const int rB = wn * 32 + (lane & 7) + ((lane >> 4) & 1) * 8;
    const int cB = (lane >> 3) & 1;

    float acc[4][4][4];
    #pragma unroll
    for (int a = 0; a < 4; a++)
        #pragma unroll
        for (int b = 0; b < 4; b++)
            #pragma unroll
            for (int c = 0; c < 4; c++) acc[a][b][c] = 0.f;

    cp_stage(sm, 0, 0, tid, i0, j0);
    CP_COMMIT();

    for (int it = 0; it < 16; it++) {
        if (it + 1 < 16) { cp_stage(sm, 1 - (it & 1), it + 1, tid, i0, j0); CP_COMMIT(); CP_WAIT(1); }
        else CP_WAIT(0);
        __syncthreads();

        uint32_t Ah = smem_u32(sm + (it & 1) * STG);
        uint32_t Al = Ah + BUF, Bh = Ah + 2 * BUF, Bl = Ah + 3 * BUF;
        #pragma unroll
        for (int ks = 0; ks < 2; ks++) {
            uint32_t af[4][4], bh[4][2], bl[4][2];
            #pragma unroll
            for (int mt = 0; mt < 4; mt++) LDSM4(af[mt], Ah + swz(rA + mt * 16, cA + 2 * ks));
            #pragma unroll
            for (int p = 0; p < 2; p++) {
                uint32_t r4[4];
                LDSM4(r4, Bh + swz(rB + p * 16, cB + 2 * ks));
                bh[2 * p][0] = r4[0]; bh[2 * p][1] = r4[1];
                bh[2 * p + 1][0] = r4[2]; bh[2 * p + 1][1] = r4[3];
                LDSM4(r4, Bl + swz(rB + p * 16, cB + 2 * ks));
                bl[2 * p][0] = r4[0]; bl[2 * p][1] = r4[1];
                bl[2 * p + 1][0] = r4[2]; bl[2 * p + 1][1] = r4[3];
            }
            #pragma unroll
            for (int mt = 0; mt < 4; mt++)
                #pragma unroll
                for (int nt = 0; nt < 4; nt++) mma16(acc[mt][nt], af[mt], bh[nt]);   // hi*hi
            #pragma unroll
            for (int mt = 0; mt < 4; mt++)
                #pragma unroll
                for (int nt = 0; nt < 4; nt++) mma16(acc[mt][nt], af[mt], bl[nt]);   // hi*lo
            #pragma unroll
            for (int mt = 0; mt < 4; mt++) LDSM4(af[mt], Al + swz(rA + mt * 16, cA + 2 * ks));
            #pragma unroll
            for (int mt = 0; mt < 4; mt++)
                #pragma unroll
                for (int nt = 0; nt < 4; nt++) mma16(acc[mt][nt], af[mt], bh[nt]);   // lo*hi
        }
        __syncthreads();
    }

    float* epi = reinterpret_cast<float*>(sm);
    #pragma unroll
    for (int mt = 0; mt < 4; mt++)
        #pragma unroll
        for (int nt = 0; nt < 4; nt++) {
            int r0 = wm * 64 + mt * 16 + l4;
            int c0 = wn * 32 + nt * 8 + lm * 2;
            #pragma unroll
            for (int i = 0; i < 4; i++) {
                int r = r0 + ((i >> 1) << 3);
                int c = c0 + (i & 1);
                float d = fmaxf(fmaf(-2.0f, acc[mt][nt][i], s_sqi[r] + s_sqj[c]), 0.0f);
                epi[r * 128 + ((c & ~31) | ((c ^ SWI(r)) & 31))] = d;
            }
        }
    __syncthreads();
    for (int idx = tid; idx < 4096; idx += 256) {
        int r = idx >> 5, c4 = (idx & 31) << 2, sw = SWI(r);
        float4 o;
        o.x = epi[r * 128 + (((c4 + 0) & ~31) | (((c4 + 0) ^ sw) & 31))];
        o.y = epi[r * 128 + (((c4 + 1) & ~31) | (((c4 + 1) ^ sw) & 31))];
        o.z = epi[r * 128 + (((c4 + 2) & ~31) | (((c4 + 2) ^ sw) & 31))];
        o.w = epi[r * 128 + (((c4 + 3) & ~31) | (((c4 + 3) ^ sw) & 31))];
        *reinterpret_cast<float4*>(g_d2 + (size_t)(i0 + r) * N + j0 + c4) = o;
    }
    for (int idx = tid; idx < 4096; idx += 256) {
        int c = idx >> 5, r4 = (idx & 31) << 2;
        float4 o;
        o.x = epi[(r4 + 0) * 128 + ((c & ~31) | ((c ^ SWI(r4 + 0)) & 31))];
        o.y = epi[(r4 + 1) * 128 + ((c & ~31) | ((c ^ SWI(r4 + 1)) & 31))];
        o.z = epi[(r4 + 2) * 128 + ((c & ~31) | ((c ^ SWI(r4 + 2)) & 31))];
        o.w = epi[(r4 + 3) * 128 + ((c & ~31) | ((c ^ SWI(r4 + 3)) & 31))];
        *reinterpret_cast<float4*>(g_d2 + (size_t)(j0 + c) * N + i0 + r4) = o;
    }
}

// ---------------- select + scatter: threshold, then sparse symmetric output ----------------
__global__ void __launch_bounds__(512) select_kernel(float* __restrict__ outp) {
    const int row = blockIdx.x, tid = threadIdx.x;
    const int warp = tid >> 5, lane = tid & 31;
    __shared__ unsigned bins[2048];
    __shared__ float cand[1024];
    __shared__ unsigned s_cnt, s_bin, s_below;
    __shared__ unsigned wsum[16];
    __shared__ float s_tv;

    float f[8];
    {
        const float4* p = reinterpret_cast<const float4*>(g_d2 + (size_t)row * N);
        #pragma unroll
        for (int q = 0; q < 2; q++) {
            float4 v = p[tid + 512 * q];
            f[q * 4 + 0] = v.x; f[q * 4 + 1] = v.y; f[q * 4 + 2] = v.z; f[q * 4 + 3] = v.w;
        }
    }
    #pragma unroll
    for (int i = 0; i < 4; i++) bins[tid + 512 * i] = 0;
    if (tid == 0) s_cnt = 0;
    __syncthreads();
    #pragma unroll
    for (int q = 0; q < 8; q++) atomicAdd(&bins[min((int)f[q], 2047)], 1u);
    __syncthreads();

    unsigned b4[4], loc = 0;
    #pragma unroll
    for (int i = 0; i < 4; i++) { b4[i] = bins[tid * 4 + i]; loc += b4[i]; }
    unsigned sc = loc;
    #pragma unroll
    for (int o = 1; o < 32; o <<= 1) { unsigned x = __shfl_up_sync(0xffffffffu, sc, o); if (lane >= o) sc += x; }
    if (lane == 31) wsum[warp] = sc;
    __syncthreads();
    if (tid < 32) {
        unsigned v = (lane < 16) ? wsum[lane] : 0u, s = v;
        #pragma unroll
        for (int o = 1; o < 16; o <<= 1) { unsigned x = __shfl_up_sync(0xffffffffu, s, o); if (lane >= o) s += x; }
        if (lane < 16) wsum[lane] = s - v;
    }
    __syncthreads();
    unsigned before = wsum[warp] + sc - loc;
    if (before < KSEL && before + loc >= KSEL) {
        unsigned cum = before;
        #pragma unroll
        for (int i = 0; i < 4; i++) {
            if (cum + b4[i] >= KSEL) { s_bin = tid * 4 + i; s_below = cum; break; }
            cum += b4[i];
        }
    }
    __syncthreads();
    const unsigned b = s_bin, rp = KSEL - s_below;
    #pragma unroll
    for (int q = 0; q < 8; q++)
        if ((unsigned)min((int)f[q], 2047) == b) {
            unsigned id = atomicAdd(&s_cnt, 1u);
            if (id < 1024) cand[id] = f[q];
        }
    __syncthreads();
    const unsigned c = min(s_cnt, 1024u);
    for (unsigned i = tid; i < c; i += 512) {
        float v = cand[i];
        unsigned less = 0, eq = 0;
        for (unsigned j = 0; j < c; j++) { float w = cand[j]; less += (w < v); eq += (w == v); }
        if (less < rp && less + eq >= rp) s_tv = v;
    }
    __syncthreads();

    // sparse scatter: w = 0.5*exp(-d*inv) into out[row][col] and out[col][row]
    const float tv = s_tv;
    float scale = sqrtf(fmaxf(tv, 1e-12f));
    float denom = fmaxf(scale, 1e-8f);
    const float inv = 1.0f / (denom * denom);
    #pragma unroll
    for (int q4 = 0; q4 < 2; q4++)
        #pragma unroll
        for (int e = 0; e < 4; e++) {
            float d = f[q4 * 4 + e];
            if (d <= tv) {
                int col = 4 * (tid + 512 * q4) + e;
                float w = 0.5f * __expf(-d * inv);
                atomicAdd(outp + (size_t)row * N + col, w);
                atomicAdd(outp + (size_t)col * N + row, w);
            }
        }
}

// ---------------- launch ----------------
extern "C" void kernel_launch(void* const* d_in, const int* in_sizes, int n_in,
                              void* d_out, int out_size) {
    const float* X = (const float*)d_in[0];
    float* outp = (float*)d_out;
    const int smem = 2 * STG;
    cudaFuncSetAttribute(gemm_kernel, cudaFuncAttributeMaxDynamicSharedMemorySize, smem);

    zero_kernel<<<(size_t)N * N / 8 / 256, 256>>>(outp);
    convnorm_kernel<<<N, 128>>>(X);
    gemm_kernel<<<528, 256, smem>>>();
    select_kernel<<<N, 512>>>(outp);
}

// round 12
// speedup vs baseline: 1.0973x; 1.0610x over previous
#include <cuda_runtime.h>
#include <cuda_fp16.h>
#include <cstdint>

#define N 4096
#define K 512
#define KSEL 31

__device__ float  g_d2[(size_t)N * N];
__device__ float  g_sq[N];
__device__ __half g_Xhi[(size_t)N * K];
__device__ __half g_Xlo[(size_t)N * K];
__device__ int      g_cols[(size_t)N * 64];
__device__ float    g_ws[(size_t)N * 64];
__device__ unsigned g_cnt[N];

__device__ __forceinline__ uint32_t smem_u32(const void* p) {
    uint32_t a;
    asm("{ .reg .u64 t; cvta.to.shared.u64 t, %1; cvt.u32.u64 %0, t; }" : "=r"(a) : "l"(p));
    return a;
}
#define CP_COMMIT() asm volatile("cp.async.commit_group;" ::: "memory")
#define CP_WAIT(n)  asm volatile("cp.async.wait_group %0;" :: "n"(n) : "memory")

__device__ __forceinline__ void mma16(float* c, const uint32_t* a, const uint32_t* b) {
    asm("mma.sync.aligned.m16n8k16.row.col.f32.f16.f16.f32 "
        "{%0,%1,%2,%3}, {%4,%5,%6,%7}, {%8,%9}, {%0,%1,%2,%3};"
        : "+f"(c[0]), "+f"(c[1]), "+f"(c[2]), "+f"(c[3])
        : "r"(a[0]), "r"(a[1]), "r"(a[2]), "r"(a[3]), "r"(b[0]), "r"(b[1]));
}
#define LDSM4(r, addr) \
    asm volatile("ldmatrix.sync.aligned.m8n8.x4.shared.b16 {%0,%1,%2,%3}, [%4];" \
        : "=r"((r)[0]), "=r"((r)[1]), "=r"((r)[2]), "=r"((r)[3]) : "r"(addr))

#define SWI(i) ((((i) >> 2) + (((i) & 3) << 3)) & 31)
__device__ __forceinline__ uint32_t swz(int r, int c) {
    return (uint32_t)(r * 64 + ((c ^ ((r >> 1) & 3)) << 4));
}

// ---------------- fused convert + norms ----------------
__global__ void __launch_bounds__(128) convnorm_kernel(const float* __restrict__ X) {
    int row = blockIdx.x, t = threadIdx.x;
    float4 v = reinterpret_cast<const float4*>(X + (size_t)row * K)[t];
    __half hx = __float2half_rn(v.x), hy = __float2half_rn(v.y);
    __half hz = __float2half_rn(v.z), hw = __float2half_rn(v.w);
    __half lx = __float2half_rn(v.x - __half2float(hx));
    __half ly = __float2half_rn(v.y - __half2float(hy));
    __half lz = __float2half_rn(v.z - __half2float(hz));
    __half lw = __float2half_rn(v.w - __half2float(hw));
    __half2* ph = reinterpret_cast<__half2*>(g_Xhi + (size_t)row * K);
    __half2* pl = reinterpret_cast<__half2*>(g_Xlo + (size_t)row * K);
    ph[t * 2 + 0] = __halves2half2(hx, hy); ph[t * 2 + 1] = __halves2half2(hz, hw);
    pl[t * 2 + 0] = __halves2half2(lx, ly); pl[t * 2 + 1] = __halves2half2(lz, lw);

    float s = v.x * v.x + v.y * v.y + v.z * v.z + v.w * v.w;
    #pragma unroll
    for (int o = 16; o; o >>= 1) s += __shfl_xor_sync(0xffffffffu, s, o);
    __shared__ float ws[4];
    if ((t & 31) == 0) ws[t >> 5] = s;
    __syncthreads();
    if (t == 0) g_sq[row] = ws[0] + ws[1] + ws[2] + ws[3];
}

// ---------------- GEMM via mma.sync fp16 (3-term split) ----------------
#define STG 32768
#define BUF 8192

__device__ __forceinline__ void cp_stage(char* sm, int s, int it, int tid, int i0, int j0) {
    char* base = sm + s * STG;
    #pragma unroll
    for (int q = 0; q < 8; q++) {
        int idx = tid + 256 * q;
        int buf = idx >> 9, r = (idx >> 2) & 127, c = idx & 3;
        const __half* src = ((buf & 1) ? g_Xlo : g_Xhi)
                          + (size_t)(((buf < 2) ? i0 : j0) + r) * K + it * 32 + c * 8;
        uint32_t dst = smem_u32(base + buf * BUF) + swz(r, c);
        asm volatile("cp.async.cg.shared.global [%0], [%1], 16;" :: "r"(dst), "l"(src));
    }
}

__global__ void __launch_bounds__(256, 2) gemm_kernel() {
    __shared__ float s_sqi[128], s_sqj[128];
    extern __shared__ char sm[];

    int t = blockIdx.x;
    int by = (int)(32.5f - sqrtf(32.5f * 32.5f - 2.0f * (float)t));
    while (by * (65 - by) / 2 > t) by--;
    while ((by + 1) * (64 - by) / 2 <= t) by++;
    int bx = by + (t - by * (65 - by) / 2);
    const int i0 = by * 128, j0 = bx * 128;

    const int tid = threadIdx.x;
    const int warp = tid >> 5, lane = tid & 31;
    const int wm = warp & 1, wn = warp >> 1;
    const int l4 = lane >> 2, lm = lane & 3;

    if (tid < 128) { s_sqi[tid] = g_sq[i0 + tid]; s_sqj[tid] = g_sq[j0 + tid]; }

    const int rA = wm * 64 + (lane & 7) + ((lane >> 3) & 1) * 8;
    const int cA = (lane >> 4) & 1;
    const int rB = wn * 32 + (lane & 7) + ((lane >> 4) & 1) * 8;
    const int cB = (lane >> 3) & 1;

    float acc[4][4][4];
    #pragma unroll
    for (int a = 0; a < 4; a++)
        #pragma unroll
        for (int b = 0; b < 4; b++)
            #pragma unroll
            for (int c = 0; c < 4; c++) acc[a][b][c] = 0.f;

    cp_stage(sm, 0, 0, tid, i0, j0);
    CP_COMMIT();

    for (int it = 0; it < 16; it++) {
        if (it + 1 < 16) { cp_stage(sm, 1 - (it & 1), it + 1, tid, i0, j0); CP_COMMIT(); CP_WAIT(1); }
        else CP_WAIT(0);
        __syncthreads();

        uint32_t Ah = smem_u32(sm + (it & 1) * STG);
        uint32_t Al = Ah + BUF, Bh = Ah + 2 * BUF, Bl = Ah + 3 * BUF;
        #pragma unroll
        for (int ks = 0; ks < 2; ks++) {
            uint32_t af[4][4], bh[4][2], bl[4][2];
            #pragma unroll
            for (int mt = 0; mt < 4; mt++) LDSM4(af[mt], Ah + swz(rA + mt * 16, cA + 2 * ks));
            #pragma unroll
            for (int p = 0; p < 2; p++) {
                uint32_t r4[4];
                LDSM4(r4, Bh + swz(rB + p * 16, cB + 2 * ks));
                bh[2 * p][0] = r4[0]; bh[2 * p][1] = r4[1];
                bh[2 * p + 1][0] = r4[2]; bh[2 * p + 1][1] = r4[3];
                LDSM4(r4, Bl + swz(rB + p * 16, cB + 2 * ks));
                bl[2 * p][0] = r4[0]; bl[2 * p][1] = r4[1];
                bl[2 * p + 1][0] = r4[2]; bl[2 * p + 1][1] = r4[3];
            }
            #pragma unroll
            for (int mt = 0; mt < 4; mt++)
                #pragma unroll
                for (int nt = 0; nt < 4; nt++) mma16(acc[mt][nt], af[mt], bh[nt]);   // hi*hi
            #pragma unroll
            for (int mt = 0; mt < 4; mt++)
                #pragma unroll
                for (int nt = 0; nt < 4; nt++) mma16(acc[mt][nt], af[mt], bl[nt]);   // hi*lo
            #pragma unroll
            for (int mt = 0; mt < 4; mt++) LDSM4(af[mt], Al + swz(rA + mt * 16, cA + 2 * ks));
            #pragma unroll
            for (int mt = 0; mt < 4; mt++)
                #pragma unroll
                for (int nt = 0; nt < 4; nt++) mma16(acc[mt][nt], af[mt], bh[nt]);   // lo*hi
        }
        __syncthreads();
    }

    float* epi = reinterpret_cast<float*>(sm);
    #pragma unroll
    for (int mt = 0; mt < 4; mt++)
        #pragma unroll
        for (int nt = 0; nt < 4; nt++) {
            int r0 = wm * 64 + mt * 16 + l4;
            int c0 = wn * 32 + nt * 8 + lm * 2;
            #pragma unroll
            for (int i = 0; i < 4; i++) {
                int r = r0 + ((i >> 1) << 3);
                int c = c0 + (i & 1);
                float d = fmaxf(fmaf(-2.0f, acc[mt][nt][i], s_sqi[r] + s_sqj[c]), 0.0f);
                epi[r * 128 + ((c & ~31) | ((c ^ SWI(r)) & 31))] = d;
            }
        }
    __syncthreads();
    for (int idx = tid; idx < 4096; idx += 256) {
        int r = idx >> 5, c4 = (idx & 31) << 2, sw = SWI(r);
        float4 o;
        o.x = epi[r * 128 + (((c4 + 0) & ~31) | (((c4 + 0) ^ sw) & 31))];
        o.y = epi[r * 128 + (((c4 + 1) & ~31) | (((c4 + 1) ^ sw) & 31))];
        o.z = epi[r * 128 + (((c4 + 2) & ~31) | (((c4 + 2) ^ sw) & 31))];
        o.w = epi[r * 128 + (((c4 + 3) & ~31) | (((c4 + 3) ^ sw) & 31))];
        *reinterpret_cast<float4*>(g_d2 + (size_t)(i0 + r) * N + j0 + c4) = o;
    }
    for (int idx = tid; idx < 4096; idx += 256) {
        int c = idx >> 5, r4 = (idx & 31) << 2;
        float4 o;
        o.x = epi[(r4 + 0) * 128 + ((c & ~31) | ((c ^ SWI(r4 + 0)) & 31))];
        o.y = epi[(r4 + 1) * 128 + ((c & ~31) | ((c ^ SWI(r4 + 1)) & 31))];
        o.z = epi[(r4 + 2) * 128 + ((c & ~31) | ((c ^ SWI(r4 + 2)) & 31))];
        o.w = epi[(r4 + 3) * 128 + ((c & ~31) | ((c ^ SWI(r4 + 3)) & 31))];
        *reinterpret_cast<float4*>(g_d2 + (size_t)(j0 + c) * N + i0 + r4) = o;
    }
}

// ---------------- select + dense row write + pair record ----------------
__global__ void __launch_bounds__(512) select_kernel(float* __restrict__ outp) {
    const int row = blockIdx.x, tid = threadIdx.x;
    const int warp = tid >> 5, lane = tid & 31;
    __shared__ unsigned bins[2048];
    __shared__ float cand[1024];
    __shared__ unsigned s_cnt, s_bin, s_below, s_pcnt;
    __shared__ unsigned wsum[16];
    __shared__ float s_tv;

    float f[8];
    {
        const float4* p = reinterpret_cast<const float4*>(g_d2 + (size_t)row * N);
        #pragma unroll
        for (int q = 0; q < 2; q++) {
            float4 v = p[tid + 512 * q];
            f[q * 4 + 0] = v.x; f[q * 4 + 1] = v.y; f[q * 4 + 2] = v.z; f[q * 4 + 3] = v.w;
        }
    }
    #pragma unroll
    for (int i = 0; i < 4; i++) bins[tid + 512 * i] = 0;
    if (tid == 0) { s_cnt = 0; s_pcnt = 0; }
    __syncthreads();
    #pragma unroll
    for (int q = 0; q < 8; q++) atomicAdd(&bins[min((int)f[q], 2047)], 1u);
    __syncthreads();

    unsigned b4[4], loc = 0;
    #pragma unroll
    for (int i = 0; i < 4; i++) { b4[i] = bins[tid * 4 + i]; loc += b4[i]; }
    unsigned sc = loc;
    #pragma unroll
    for (int o = 1; o < 32; o <<= 1) { unsigned x = __shfl_up_sync(0xffffffffu, sc, o); if (lane >= o) sc += x; }
    if (lane == 31) wsum[warp] = sc;
    __syncthreads();
    if (tid < 32) {
        unsigned v = (lane < 16) ? wsum[lane] : 0u, s = v;
        #pragma unroll
        for (int o = 1; o < 16; o <<= 1) { unsigned x = __shfl_up_sync(0xffffffffu, s, o); if (lane >= o) s += x; }
        if (lane < 16) wsum[lane] = s - v;
    }
    __syncthreads();
    unsigned before = wsum[warp] + sc - loc;
    if (before < KSEL && before + loc >= KSEL) {
        unsigned cum = before;
        #pragma unroll
        for (int i = 0; i < 4; i++) {
            if (cum + b4[i] >= KSEL) { s_bin = tid * 4 + i; s_below = cum; break; }
            cum += b4[i];
        }
    }
    __syncthreads();
    const unsigned b = s_bin, rp = KSEL - s_below;
    #pragma unroll
    for (int q = 0; q < 8; q++)
        if ((unsigned)min((int)f[q], 2047) == b) {
            unsigned id = atomicAdd(&s_cnt, 1u);
            if (id < 1024) cand[id] = f[q];
        }
    __syncthreads();
    const unsigned c = min(s_cnt, 1024u);
    for (unsigned i = tid; i < c; i += 512) {
        float v = cand[i];
        unsigned less = 0, eq = 0;
        for (unsigned j = 0; j < c; j++) { float w = cand[j]; less += (w < v); eq += (w == v); }
        if (less < rp && less + eq >= rp) s_tv = v;
    }
    __syncthreads();

    // threshold known: dense row write (w or 0) from registers + record pairs
    const float tv = s_tv;
    float scale = sqrtf(fmaxf(tv, 1e-12f));
    float denom = fmaxf(scale, 1e-8f);
    const float inv = 1.0f / (denom * denom);
    #pragma unroll
    for (int q = 0; q < 2; q++) {
        int colbase = 4 * (tid + 512 * q);
        float ov[4];
        #pragma unroll
        for (int e = 0; e < 4; e++) {
            float d = f[q * 4 + e];
            float w = 0.f;
            if (d <= tv) {
                w = 0.5f * __expf(-d * inv);
                unsigned id = atomicAdd(&s_pcnt, 1u);
                if (id < 64) { g_cols[(size_t)row * 64 + id] = colbase + e; g_ws[(size_t)row * 64 + id] = w; }
            }
            ov[e] = w;
        }
        *reinterpret_cast<float4*>(outp + (size_t)row * N + colbase) =
            make_float4(ov[0], ov[1], ov[2], ov[3]);
    }
    __syncthreads();
    if (tid == 0) g_cnt[row] = min(s_pcnt, 64u);
}

// ---------------- scatter transpose contributions ----------------
__global__ void __launch_bounds__(256) scatter_kernel(float* __restrict__ outp) {
    int row = blockIdx.x * 8 + (threadIdx.x >> 5);
    int lane = threadIdx.x & 31;
    unsigned cnt = g_cnt[row];
    for (unsigned i = lane; i < cnt; i += 32) {
        int col  = g_cols[(size_t)row * 64 + i];
        float w  = g_ws[(size_t)row * 64 + i];
        atomicAdd(outp + (size_t)col * N + row, w);
    }
}

// ---------------- launch ----------------
extern "C" void kernel_launch(void* const* d_in, const int* in_sizes, int n_in,
                              void* d_out, int out_size) {
    const float* X = (const float*)d_in[0];
    float* outp = (float*)d_out;
    const int smem = 2 * STG;
    cudaFuncSetAttribute(gemm_kernel, cudaFuncAttributeMaxDynamicSharedMemorySize, smem);

    convnorm_kernel<<<N, 128>>>(X);
    gemm_kernel<<<528, 256, smem>>>();
    select_kernel<<<N, 512>>>(outp);
    scatter_kernel<<<N / 8, 256>>>(outp);
}